// round 6
// baseline (speedup 1.0000x reference)
#include <cuda_runtime.h>

// loss = M * (1/(999N) + 1/N), M = #pixels where trunc-index(r) != trunc-index(t).
// Exact-fit (N % 512 == 0): 176 blocks x 128 threads for N=90112 -> all 148
// SMs active in wave 1 (88x256 left 60 SMs idle). One float4-pair per thread,
// straight-line, __ldcg (L1 flushed per launch; L2-resident across replays).
// Per-warp REDUX -> fused 64-bit (count<<32 | done) atomic; last warp
// finalizes with host reciprocals and resets via plain strong store (graph
// replays are sequential; kernel boundary orders it). Guarded fallback for
// other N.

__device__ unsigned long long g_acc = 0ull;  // [count:32 | warps_done:32]

static __device__ __forceinline__ int quant_idx(float x) {
    // match reference: x*1000 - 1, clamp below at 0, truncate (floor for v>=0)
    float v = __fsub_rn(__fmul_rn(x, 1000.0f), 1.0f);
    v = v < 0.0f ? 0.0f : v;
    return (int)v;
}

static __device__ __forceinline__ unsigned int count4(float4 a, float4 b) {
    unsigned int c = 0;
    c += (quant_idx(a.x) != quant_idx(b.x));
    c += (quant_idx(a.y) != quant_idx(b.y));
    c += (quant_idx(a.z) != quant_idx(b.z));
    c += (quant_idx(a.w) != quant_idx(b.w));
    return c;
}

static __device__ __forceinline__ void warp_commit(unsigned int cnt,
                                                   unsigned int total_warps,
                                                   float* out, float inv_zero,
                                                   float inv_nonzero) {
    cnt = __reduce_add_sync(0xFFFFFFFFu, cnt);
    if ((threadIdx.x & 31) == 0) {
        unsigned long long old =
            atomicAdd(&g_acc, ((unsigned long long)cnt << 32) | 1ull);
        if ((unsigned int)(old & 0xFFFFFFFFull) == total_warps - 1) {
            unsigned int M = (unsigned int)(old >> 32) + cnt;
            float fM = (float)M;
            out[0] = __fmaf_rn(fM, inv_zero, fM * inv_nonzero);
            // reset for next replay: plain strong store (no atomic round-trip;
            // graph replays are sequential, kernel boundary orders visibility)
            asm volatile("st.global.release.gpu.u64 [%0], 0;"
                         :: "l"(&g_acc) : "memory");
        }
    }
}

// Exact-fit path: grid*128 threads == N/4 exactly. Straight-line, no guards.
__global__ void __launch_bounds__(128)
true3d_loss_exact(const float4* __restrict__ r4, const float4* __restrict__ t4,
                  float* __restrict__ out, unsigned int total_warps,
                  float inv_zero, float inv_nonzero) {
    const int i = blockIdx.x * 128 + threadIdx.x;
    float4 a = __ldcg(&r4[i]);
    float4 b = __ldcg(&t4[i]);
    warp_commit(count4(a, b), total_warps, out, inv_zero, inv_nonzero);
}

// Generic guarded fallback for N not a multiple of 512.
__global__ void __launch_bounds__(256)
true3d_loss_generic(const float* __restrict__ r, const float* __restrict__ t,
                    float* __restrict__ out, int N, unsigned int total_warps,
                    float inv_zero, float inv_nonzero) {
    const int tid = blockIdx.x * blockDim.x + threadIdx.x;
    const int stride = gridDim.x * blockDim.x;
    const int N4 = N >> 2;
    const float4* __restrict__ r4 = (const float4*)r;
    const float4* __restrict__ t4 = (const float4*)t;

    unsigned int cnt = 0;
    for (int i = tid; i < N4; i += stride)
        cnt += count4(__ldcg(&r4[i]), __ldcg(&t4[i]));
    for (int i = (N4 << 2) + tid; i < N; i += stride)
        cnt += (quant_idx(__ldcg(&r[i])) != quant_idx(__ldcg(&t[i])));

    warp_commit(cnt, total_warps, out, inv_zero, inv_nonzero);
}

extern "C" void kernel_launch(void* const* d_in, const int* in_sizes, int n_in,
                              void* d_out, int out_size) {
    const float* rec = (const float*)d_in[0];
    const float* tgt = (const float*)d_in[1];
    float* out = (float*)d_out;
    const int N = in_sizes[0];

    const float fN = (float)N;
    const float inv_zero = 1.0f / (999.0f * fN);
    const float inv_nonzero = 1.0f / fN;

    if (N > 0 && (N & 511) == 0) {
        const int blocks = N / 512;                     // 176 for N=90112
        const unsigned int total_warps = (unsigned int)blocks * 4u;
        true3d_loss_exact<<<blocks, 128>>>((const float4*)rec,
                                           (const float4*)tgt, out,
                                           total_warps, inv_zero, inv_nonzero);
    } else {
        const int threads = 256;
        int blocks = (N / 4 + threads - 1) / threads;
        if (blocks < 1) blocks = 1;
        if (blocks > 1024) blocks = 1024;
        const unsigned int total_warps = (unsigned int)blocks * (threads / 32);
        true3d_loss_generic<<<blocks, threads>>>(rec, tgt, out, N, total_warps,
                                                 inv_zero, inv_nonzero);
    }
}

// round 7
// speedup vs baseline: 1.0048x; 1.0048x over previous
#include <cuda_runtime.h>

// loss = M * scale, scale = 1/(999N) + 1/N (host-precomputed),
// M = #pixels where trunc-index(r) != trunc-index(t).
// Best-measured config: 88 blocks x 256 threads (exact fit, N % 1024 == 0),
// one float4-pair per thread, straight-line, __ldcg (L1 flushed per launch;
// inputs L2-resident across graph replays). Per-warp REDUX -> fused 64-bit
// (count<<32 | warps_done) atomic; last warp writes M*scale and resets via
// plain release store (graph replays are sequential). Guarded fallback for
// other N. Wall time is launch/replay-overhead bound (~6.6us floor).

__device__ unsigned long long g_acc = 0ull;  // [count:32 | warps_done:32]

static __device__ __forceinline__ int quant_idx(float x) {
    // match reference: x*1000 - 1, clamp below at 0, truncate (floor for v>=0)
    float v = __fsub_rn(__fmul_rn(x, 1000.0f), 1.0f);
    v = v < 0.0f ? 0.0f : v;
    return (int)v;
}

static __device__ __forceinline__ unsigned int count4(float4 a, float4 b) {
    unsigned int c = 0;
    c += (quant_idx(a.x) != quant_idx(b.x));
    c += (quant_idx(a.y) != quant_idx(b.y));
    c += (quant_idx(a.z) != quant_idx(b.z));
    c += (quant_idx(a.w) != quant_idx(b.w));
    return c;
}

static __device__ __forceinline__ void warp_commit(unsigned int cnt,
                                                   unsigned int total_warps,
                                                   float* out, float scale) {
    cnt = __reduce_add_sync(0xFFFFFFFFu, cnt);
    if ((threadIdx.x & 31) == 0) {
        unsigned long long old =
            atomicAdd(&g_acc, ((unsigned long long)cnt << 32) | 1ull);
        if ((unsigned int)(old & 0xFFFFFFFFull) == total_warps - 1) {
            unsigned int M = (unsigned int)(old >> 32) + cnt;
            out[0] = __fmul_rn((float)M, scale);
            // reset for next replay: plain release store, no atomic round-trip
            asm volatile("st.global.release.gpu.u64 [%0], 0;"
                         :: "l"(&g_acc) : "memory");
        }
    }
}

// Exact-fit path: grid*256 threads == N/4 exactly. Straight-line, no guards.
__global__ void __launch_bounds__(256)
true3d_loss_exact(const float4* __restrict__ r4, const float4* __restrict__ t4,
                  float* __restrict__ out, unsigned int total_warps,
                  float scale) {
    const int i = blockIdx.x * 256 + threadIdx.x;
    float4 a = __ldcg(&r4[i]);
    float4 b = __ldcg(&t4[i]);
    warp_commit(count4(a, b), total_warps, out, scale);
}

// Generic guarded fallback for N not a multiple of 1024.
__global__ void __launch_bounds__(256)
true3d_loss_generic(const float* __restrict__ r, const float* __restrict__ t,
                    float* __restrict__ out, int N, unsigned int total_warps,
                    float scale) {
    const int tid = blockIdx.x * blockDim.x + threadIdx.x;
    const int stride = gridDim.x * blockDim.x;
    const int N4 = N >> 2;
    const float4* __restrict__ r4 = (const float4*)r;
    const float4* __restrict__ t4 = (const float4*)t;

    unsigned int cnt = 0;
    for (int i = tid; i < N4; i += stride)
        cnt += count4(__ldcg(&r4[i]), __ldcg(&t4[i]));
    for (int i = (N4 << 2) + tid; i < N; i += stride)
        cnt += (quant_idx(__ldcg(&r[i])) != quant_idx(__ldcg(&t[i])));

    warp_commit(cnt, total_warps, out, scale);
}

extern "C" void kernel_launch(void* const* d_in, const int* in_sizes, int n_in,
                              void* d_out, int out_size) {
    const float* rec = (const float*)d_in[0];
    const float* tgt = (const float*)d_in[1];
    float* out = (float*)d_out;
    const int N = in_sizes[0];

    const float fN = (float)N;
    const float scale = 1.0f / (999.0f * fN) + 1.0f / fN;

    if (N > 0 && (N & 1023) == 0) {
        const int blocks = N / 1024;                    // 88 for N=90112
        const unsigned int total_warps = (unsigned int)blocks * 8u;
        true3d_loss_exact<<<blocks, 256>>>((const float4*)rec,
                                           (const float4*)tgt, out,
                                           total_warps, scale);
    } else {
        const int threads = 256;
        int blocks = (N / 4 + threads - 1) / threads;
        if (blocks < 1) blocks = 1;
        if (blocks > 1024) blocks = 1024;
        const unsigned int total_warps = (unsigned int)blocks * (threads / 32);
        true3d_loss_generic<<<blocks, threads>>>(rec, tgt, out, N, total_warps,
                                                 scale);
    }
}